// round 2
// baseline (speedup 1.0000x reference)
#include <cuda_runtime.h>
#include <cstdint>

// Problem constants
#define BB   1024          // batch
#define LL   128           // latent dim (also output dim)
#define PP   32            // pert dim
#define KTOT (LL*PP*PP)    // 131072

#define MTILES  8          // 1024 / 128
#define SPLITS  16         // l-splits, 8 l's each
#define LPER    (LL/SPLITS) // 8

// 8 MB split-K partial buffer (device global: allocation-free scratch)
__device__ float g_partial[SPLITS * BB * LL];

// ---------------- f32x2 packed-math helpers ----------------
__device__ __forceinline__ unsigned long long dup2(float x) {
    unsigned long long r;
    asm("mov.b64 %0, {%1,%1};" : "=l"(r) : "f"(x));
    return r;
}
__device__ __forceinline__ void unpack2(unsigned long long v, float& x, float& y) {
    asm("mov.b64 {%0,%1}, %2;" : "=f"(x), "=f"(y) : "l"(v));
}
#define FMA2(d, a, b) asm("fma.rn.f32x2 %0, %1, %2, %0;" : "+l"(d) : "l"(a), "l"(b))

// ---------------- cp.async helpers ----------------
__device__ __forceinline__ void cp_async16(unsigned smem_addr, const void* gptr) {
    asm volatile("cp.async.cg.shared.global [%0], [%1], 16;" :: "r"(smem_addr), "l"(gptr));
}
#define CP_COMMIT() asm volatile("cp.async.commit_group;")
#define CP_WAIT0()  asm volatile("cp.async.wait_group 0;")

// SMEM layout (floats): pT[32][128] | cT[8][128] | Wsm[2][32][128]
#define SM_PT   0
#define SM_CT   (32*128)
#define SM_W    (32*128 + 8*128)
#define SMEM_FLOATS (32*128 + 8*128 + 2*32*128)
#define SMEM_BYTES  (SMEM_FLOATS * 4)

__global__ void __launch_bounds__(256, 1)
fipp_main_kernel(const float* __restrict__ ctrl,
                 const float* __restrict__ pert,
                 const float* __restrict__ W)
{
    extern __shared__ float smem[];
    float* pT  = smem + SM_PT;   // pT[j][m] : pert transposed for this M-tile
    float* cT  = smem + SM_CT;   // cT[ll][m]: ctrl transposed, this CTA's 8 l's
    float* Wsm = smem + SM_W;    // double-buffered 32x128 weight tile

    const int tid    = threadIdx.x;
    const int mtile  = blockIdx.x;          // 0..7
    const int split  = blockIdx.y;          // 0..15
    const int bm0    = mtile * 128;
    const int l_base = split * LPER;

    // ---- one-time loads: pert rows (transposed) and ctrl slice (transposed) ----
    if (tid < 128) {
        const int bglob = bm0 + tid;
        const float4* pr = (const float4*)(pert + (size_t)bglob * PP);
        #pragma unroll
        for (int q = 0; q < 8; q++) {
            float4 v = pr[q];
            pT[(q*4 + 0)*128 + tid] = v.x;
            pT[(q*4 + 1)*128 + tid] = v.y;
            pT[(q*4 + 2)*128 + tid] = v.z;
            pT[(q*4 + 3)*128 + tid] = v.w;
        }
        const float4* cr = (const float4*)(ctrl + (size_t)bglob * LL + l_base);
        float4 c0 = cr[0], c1 = cr[1];
        cT[0*128 + tid] = c0.x; cT[1*128 + tid] = c0.y;
        cT[2*128 + tid] = c0.z; cT[3*128 + tid] = c0.w;
        cT[4*128 + tid] = c1.x; cT[5*128 + tid] = c1.y;
        cT[6*128 + tid] = c1.z; cT[7*128 + tid] = c1.w;
    }

    // ---- lane/warp layout: warp tile 32(M) x 64(N); lane = ln*4 + lm ----
    const int lane = tid & 31;
    const int w    = tid >> 5;
    const int lm   = lane & 3;
    const int ln   = lane >> 2;
    const int wm   = w & 3;
    const int wn   = w >> 2;
    const int mb   = wm * 32 + lm * 4;   // rows mb..mb+3, mb+16..mb+19
    const int nb   = wn * 64 + ln * 4;   // cols nb..nb+3, nb+32..nb+35

    unsigned long long acc[8][4];
    #pragma unroll
    for (int m = 0; m < 8; m++)
        #pragma unroll
        for (int q = 0; q < 4; q++) acc[m][q] = 0ULL;

    // cp.async W-tile loader mapping: 32 rows x 128 cols, 16 floats/thread
    const int wk  = tid >> 3;          // row 0..31
    const int wn0 = (tid & 7) * 16;    // col start
    const unsigned swbase = (unsigned)__cvta_generic_to_shared(Wsm);

    auto issueW = [&](int ch, int buf) {
        const int ll = ch >> 5, ii = ch & 31;
        const long kb = (long)(l_base + ll) * (PP*PP) + ii * PP;
        const float* gsrc = W + (kb + wk) * 128 + wn0;
        unsigned sdst = swbase + (unsigned)(buf * 4096 + wk * 128 + wn0) * 4u;
        cp_async16(sdst,      gsrc);
        cp_async16(sdst + 16, gsrc + 4);
        cp_async16(sdst + 32, gsrc + 8);
        cp_async16(sdst + 48, gsrc + 12);
        CP_COMMIT();
    };

    issueW(0, 0);
    __syncthreads();   // cover pT/cT fill as well before first compute wait

    const int NCH = LPER * PP;   // 256 chunks of K=32
    for (int ch = 0; ch < NCH; ch++) {
        const int cur = ch & 1;
        CP_WAIT0();
        __syncthreads();
        if (ch + 1 < NCH) issueW(ch + 1, cur ^ 1);

        const float* Wc = Wsm + cur * 4096;

        unsigned long long inner[8][4];
        #pragma unroll
        for (int m = 0; m < 8; m++)
            #pragma unroll
            for (int q = 0; q < 4; q++) inner[m][q] = 0ULL;

        #pragma unroll 4
        for (int kk = 0; kk < 32; kk++) {
            const float4 a0 = *(const float4*)(pT + kk*128 + mb);
            const float4 a1 = *(const float4*)(pT + kk*128 + mb + 16);
            const ulonglong2 b0 = *(const ulonglong2*)(Wc + kk*128 + nb);
            const ulonglong2 b1 = *(const ulonglong2*)(Wc + kk*128 + nb + 32);
            const float am[8] = {a0.x, a0.y, a0.z, a0.w, a1.x, a1.y, a1.z, a1.w};
            #pragma unroll
            for (int m = 0; m < 8; m++) {
                const unsigned long long ad = dup2(am[m]);
                FMA2(inner[m][0], ad, b0.x);
                FMA2(inner[m][1], ad, b0.y);
                FMA2(inner[m][2], ad, b1.x);
                FMA2(inner[m][3], ad, b1.y);
            }
        }

        // fold s_b = c[b,l] * p[b,i] into the accumulators
        const int ll = ch >> 5, ii = ch & 31;
        const float4 c0 = *(const float4*)(cT + ll*128 + mb);
        const float4 c1 = *(const float4*)(cT + ll*128 + mb + 16);
        const float4 p0 = *(const float4*)(pT + ii*128 + mb);
        const float4 p1 = *(const float4*)(pT + ii*128 + mb + 16);
        const float sm[8] = {c0.x*p0.x, c0.y*p0.y, c0.z*p0.z, c0.w*p0.w,
                             c1.x*p1.x, c1.y*p1.y, c1.z*p1.z, c1.w*p1.w};
        #pragma unroll
        for (int m = 0; m < 8; m++) {
            const unsigned long long sd = dup2(sm[m]);
            #pragma unroll
            for (int q = 0; q < 4; q++) FMA2(acc[m][q], sd, inner[m][q]);
        }
    }

    // ---- write split-K partials ----
    float* gp = g_partial + (size_t)split * (BB * LL);
    #pragma unroll
    for (int m = 0; m < 8; m++) {
        const int mg = mb + (m & 3) + ((m >= 4) ? 16 : 0);
        float* row = gp + (size_t)(bm0 + mg) * LL;
        #pragma unroll
        for (int q = 0; q < 4; q++) {
            const int ng = nb + (q & 1) * 2 + (q >> 1) * 32;
            float2 v; unpack2(acc[m][q], v.x, v.y);
            *(float2*)(row + ng) = v;
        }
    }
}

__global__ void __launch_bounds__(256)
fipp_reduce_kernel(const float* __restrict__ bias, float* __restrict__ out)
{
    const int i4 = blockIdx.x * blockDim.x + threadIdx.x;   // 0..32767 float4s
    float4 acc = *(const float4*)(bias + ((i4 * 4) & (LL - 1)));
    #pragma unroll
    for (int s = 0; s < SPLITS; s++) {
        const float4 v = *(const float4*)(g_partial + (size_t)s * (BB * LL) + (size_t)i4 * 4);
        acc.x += v.x; acc.y += v.y; acc.z += v.z; acc.w += v.w;
    }
    *(float4*)(out + (size_t)i4 * 4) = acc;
}

extern "C" void kernel_launch(void* const* d_in, const int* in_sizes, int n_in,
                              void* d_out, int out_size)
{
    const float* ctrl = (const float*)d_in[0];   // (1024,128)
    const float* pert = (const float*)d_in[1];   // (1024,32)
    const float* W    = (const float*)d_in[2];   // (131072,128)
    const float* bias = (const float*)d_in[3];   // (128,)
    float* out = (float*)d_out;                  // (1024,128)

    cudaFuncSetAttribute(fipp_main_kernel,
                         cudaFuncAttributeMaxDynamicSharedMemorySize, SMEM_BYTES);

    fipp_main_kernel<<<dim3(MTILES, SPLITS), 256, SMEM_BYTES>>>(ctrl, pert, W);
    fipp_reduce_kernel<<<(BB * LL) / 4 / 256, 256>>>(bias, out);
}

// round 4
// speedup vs baseline: 1.3938x; 1.3938x over previous
#include <cuda_runtime.h>
#include <cstdint>

// ---------------- problem constants ----------------
#define BB 1024
#define LL 128
#define PP 32
#define SPLITS 16
#define LPER   8                  // l's per split
#define MTILES 8                  // 1024/128
#define NSTAGE 64                 // stages per CTA, stage = K=128 (one l, 4 i's)

// ---------------- device scratch (allocation-free) ----------------
__device__ float    g_partial[SPLITS * BB * LL];   // 8 MB split-K partials
__device__ uint32_t g_Wh[4096 * 2048];             // 32 MB: W-hi bf16 chunk images [chunk][n=128][k=32]
__device__ uint32_t g_Wl[4096 * 2048];             // 32 MB: W-lo

// ---------------- helpers ----------------
__device__ __forceinline__ uint32_t s2u(const void* p) {
    uint32_t a;
    asm("{ .reg .u64 t; cvta.to.shared.u64 t, %1; cvt.u32.u64 %0, t; }" : "=r"(a) : "l"(p));
    return a;
}
// pack two f32 -> bf16x2 (lo half = x0, hi half = x1)
__device__ __forceinline__ uint32_t pack_bf2(float x0, float x1) {
    uint32_t r;
    asm("cvt.rn.bf16x2.f32 %0, %1, %2;" : "=r"(r) : "f"(x1), "f"(x0));
    return r;
}
__device__ __forceinline__ void cp16(uint32_t sdst, const void* gsrc) {
    asm volatile("cp.async.cg.shared.global [%0], [%1], 16;" :: "r"(sdst), "l"(gsrc));
}
#define CP_COMMIT() asm volatile("cp.async.commit_group;")

#define LDSM4(r, a)                                                         \
    asm volatile("ldmatrix.sync.aligned.m8n8.x4.shared.b16 {%0,%1,%2,%3}, [%4];" \
                 : "=r"((r)[0]), "=r"((r)[1]), "=r"((r)[2]), "=r"((r)[3])   \
                 : "r"(a))

__device__ __forceinline__ void mma_acc(float* d, const uint32_t* a, uint32_t b0, uint32_t b1) {
    asm("mma.sync.aligned.m16n8k16.row.col.f32.bf16.bf16.f32 "
        "{%0,%1,%2,%3},{%4,%5,%6,%7},{%8,%9},{%0,%1,%2,%3};"
        : "+f"(d[0]), "+f"(d[1]), "+f"(d[2]), "+f"(d[3])
        : "r"(a[0]), "r"(a[1]), "r"(a[2]), "r"(a[3]), "r"(b0), "r"(b1));
}
__device__ __forceinline__ void mma_zinit(float* d, const uint32_t* a, uint32_t b0, uint32_t b1) {
    asm("mma.sync.aligned.m16n8k16.row.col.f32.bf16.bf16.f32 "
        "{%0,%1,%2,%3},{%4,%5,%6,%7},{%8,%9},{%10,%11,%12,%13};"
        : "=f"(d[0]), "=f"(d[1]), "=f"(d[2]), "=f"(d[3])
        : "r"(a[0]), "r"(a[1]), "r"(a[2]), "r"(a[3]), "r"(b0), "r"(b1),
          "f"(0.0f), "f"(0.0f), "f"(0.0f), "f"(0.0f));
}

// ---------------- SMEM layout (main kernel) ----------------
// stage B tile per matrix: [n=128][k=128 bf16] rows padded 256B -> 272B
#define ROWB    272
#define BMAT_SZ (128 * ROWB)        // 34816
#define BUF_SZ  (2 * BMAT_SZ)       // Wh + Wl = 69632
#define OFF_PS  (2 * BUF_SZ)        // 139264 : float pS[128][33]
#define OFF_CS  (OFF_PS + 128 * 33 * 4)
#define SMEM_TOTAL (OFF_CS + 128 * 9 * 4)   // 160768 bytes

// =====================================================================
// Prep: W fp32 [131072][128] -> per-chunk [n=128][k=32] bf16 hi/lo images
// chunk = l*32+i (4096 chunks), image = 2048 u32 (8KB)
// =====================================================================
__global__ void __launch_bounds__(256) fipp_prep_kernel(const float* __restrict__ W)
{
    __shared__ float s[32][133];
    const int c = blockIdx.x, tid = threadIdx.x;
    const float4* src = (const float4*)(W + (size_t)c * 4096);
    for (int e = tid; e < 1024; e += 256) {
        float4 v = src[e];
        int j = e >> 5, n4 = (e & 31) << 2;
        s[j][n4] = v.x; s[j][n4 + 1] = v.y; s[j][n4 + 2] = v.z; s[j][n4 + 3] = v.w;
    }
    __syncthreads();
    uint32_t* oh = g_Wh + (size_t)c * 2048;
    uint32_t* ol = g_Wl + (size_t)c * 2048;
    for (int e = tid; e < 2048; e += 256) {
        const int n = e >> 4, jw = e & 15;
        float x0 = s[2 * jw][n], x1 = s[2 * jw + 1][n];
        uint32_t h = pack_bf2(x0, x1);
        float h0 = __uint_as_float(h << 16);
        float h1 = __uint_as_float(h & 0xffff0000u);
        oh[e] = h;
        ol[e] = pack_bf2(x0 - h0, x1 - h1);
    }
}

// =====================================================================
// Main: HMMA bf16 3-GEMM split. CTA: M=128 batch rows, N=128, K=8192.
// A = p[b][j] constant in registers; per-chunk scalar s=c_l*p_i folded
// into fp32 register accumulators after each K=32 inner product.
// =====================================================================
__global__ void __launch_bounds__(256, 1)
fipp_mma_kernel(const float* __restrict__ ctrl, const float* __restrict__ pert)
{
    extern __shared__ char smem[];
    float* pS = (float*)(smem + OFF_PS);   // [128][33]
    float* cS = (float*)(smem + OFF_CS);   // [128][9]
    const uint32_t sb = s2u(smem);
    const int tid = threadIdx.x, wid = tid >> 5, lane = tid & 31;
    const int wm = wid & 3, wn = wid >> 2;
    const int g = lane >> 2, t = lane & 3;
    const int bm0 = blockIdx.x * 128, l_base = blockIdx.y * LPER;

    // one-time p (padded 33) and c (padded 9) loads
    for (int e = tid; e < 128 * 32; e += 256) {
        int r = e >> 5, j = e & 31;
        pS[r * 33 + j] = pert[(size_t)(bm0 + r) * PP + j];
    }
    for (int e = tid; e < 128 * 8; e += 256) {
        int r = e >> 3, q = e & 7;
        cS[r * 9 + q] = ctrl[(size_t)(bm0 + r) * LL + l_base + q];
    }

    // B stage loader (double buffered)
    auto issueW = [&](int st, int buf) {
        const int l = st >> 3, i0 = (st & 7) * 4;
        const size_t cb = ((size_t)(l_base + l) * 32 + i0) * 2048;
        const uint32_t* gh = g_Wh + cb;
        const uint32_t* gl = g_Wl + cb;
        const uint32_t bbase = sb + (uint32_t)buf * BUF_SZ;
        #pragma unroll
        for (int q = 0; q < 8; q++) {
            const int e = q * 256 + tid;
            const int c = e >> 9, n = (e >> 2) & 127, w4 = e & 3;
            const uint32_t d = bbase + (uint32_t)(n * ROWB + (c << 6) + (w4 << 4));
            cp16(d, gh + 4 * e);
            cp16(d + BMAT_SZ, gl + 4 * e);
        }
        CP_COMMIT();
    };

    issueW(0, 0);
    __syncthreads();   // pS/cS ready

    // constant A fragments: p hi/lo, [msub][kstep][4 regs]
    uint32_t ah[2][2][4], al[2][2][4];
    #pragma unroll
    for (int m = 0; m < 2; m++)
        #pragma unroll
        for (int ks = 0; ks < 2; ks++)
            #pragma unroll
            for (int r4 = 0; r4 < 4; r4++) {
                const int row = wm * 32 + m * 16 + g + (r4 & 1) * 8;
                const int jb  = ks * 16 + 2 * t + (r4 >> 1) * 8;
                const float x0 = pS[row * 33 + jb], x1 = pS[row * 33 + jb + 1];
                const uint32_t h = pack_bf2(x0, x1);
                ah[m][ks][r4] = h;
                al[m][ks][r4] = pack_bf2(x0 - __uint_as_float(h << 16),
                                         x1 - __uint_as_float(h & 0xffff0000u));
            }

    float acc[2][8][4];
    #pragma unroll
    for (int m = 0; m < 2; m++)
        #pragma unroll
        for (int nt = 0; nt < 8; nt++)
            #pragma unroll
            for (int k = 0; k < 4; k++) acc[m][nt][k] = 0.f;

    // ldmatrix per-thread base: lane -> (matrix, row-in-8x8)
    const int nlocal = ((lane >> 4) << 3) | (lane & 7);
    const int koffm  = ((lane >> 3) & 1) << 4;
    const uint32_t tb = (uint32_t)((wn * 64 + nlocal) * ROWB + koffm);

    for (int st = 0; st < NSTAGE; st++) {
        const int buf = st & 1;
        if (st + 1 < NSTAGE) {
            issueW(st + 1, buf ^ 1);
            asm volatile("cp.async.wait_group 1;");
        } else {
            asm volatile("cp.async.wait_group 0;");
        }
        __syncthreads();

        const int l = st >> 3, i0 = (st & 7) * 4;
        const uint32_t Bh = sb + (uint32_t)buf * BUF_SZ;
        const uint32_t Bl = Bh + BMAT_SZ;

        #pragma unroll
        for (int c = 0; c < 4; c++) {
            // per-row scale s = ctrl[l] * pert[i0+c]
            float s[4];
            #pragma unroll
            for (int k = 0; k < 4; k++) {
                const int row = wm * 32 + k * 8 + g;
                s[k] = cS[row * 9 + l] * pS[row * 33 + i0 + c];
            }

            float inner[2][8][4];
            #pragma unroll
            for (int ks = 0; ks < 2; ks++) {
                uint32_t bh[16], bl[16];
                #pragma unroll
                for (int ntp = 0; ntp < 4; ntp++) {
                    const uint32_t a = tb + (uint32_t)(ntp * 16 * ROWB + c * 64 + ks * 32);
                    LDSM4(bh + 4 * ntp, Bh + a);
                    LDSM4(bl + 4 * ntp, Bl + a);
                }
                #pragma unroll
                for (int m = 0; m < 2; m++)
                    #pragma unroll
                    for (int nt = 0; nt < 8; nt++) {
                        if (ks == 0) mma_zinit(inner[m][nt], ah[m][0], bh[2*nt], bh[2*nt+1]);
                        else         mma_acc  (inner[m][nt], ah[m][1], bh[2*nt], bh[2*nt+1]);
                        mma_acc(inner[m][nt], ah[m][ks], bl[2*nt], bl[2*nt+1]);
                        mma_acc(inner[m][nt], al[m][ks], bh[2*nt], bh[2*nt+1]);
                    }
            }
            // fold scalar into accumulators
            #pragma unroll
            for (int m = 0; m < 2; m++)
                #pragma unroll
                for (int nt = 0; nt < 8; nt++) {
                    acc[m][nt][0] += s[2*m]     * inner[m][nt][0];
                    acc[m][nt][1] += s[2*m]     * inner[m][nt][1];
                    acc[m][nt][2] += s[2*m + 1] * inner[m][nt][2];
                    acc[m][nt][3] += s[2*m + 1] * inner[m][nt][3];
                }
        }
        __syncthreads();   // protect buf before next issue overwrites
    }

    // epilogue -> split-K partials
    #pragma unroll
    for (int m = 0; m < 2; m++)
        #pragma unroll
        for (int rh = 0; rh < 2; rh++) {
            const int rowloc = wm * 32 + m * 16 + rh * 8 + g;
            float* dst = g_partial + ((size_t)blockIdx.y * BB + bm0 + rowloc) * LL;
            #pragma unroll
            for (int nt = 0; nt < 8; nt++) {
                const int col = wn * 64 + nt * 8 + 2 * t;
                float2 v;
                v.x = acc[m][nt][rh ? 2 : 0];
                v.y = acc[m][nt][rh ? 3 : 1];
                *(float2*)(dst + col) = v;
            }
        }
}

// =====================================================================
// Reduce: sum 16 split-K partials + bias
// =====================================================================
__global__ void __launch_bounds__(256)
fipp_reduce_kernel(const float* __restrict__ bias, float* __restrict__ out)
{
    const int i4 = blockIdx.x * blockDim.x + threadIdx.x;
    float4 acc = *(const float4*)(bias + ((i4 * 4) & (LL - 1)));
    #pragma unroll
    for (int s = 0; s < SPLITS; s++) {
        const float4 v = *(const float4*)(g_partial + (size_t)s * (BB * LL) + (size_t)i4 * 4);
        acc.x += v.x; acc.y += v.y; acc.z += v.z; acc.w += v.w;
    }
    *(float4*)(out + (size_t)i4 * 4) = acc;
}

extern "C" void kernel_launch(void* const* d_in, const int* in_sizes, int n_in,
                              void* d_out, int out_size)
{
    const float* ctrl = (const float*)d_in[0];   // (1024,128)
    const float* pert = (const float*)d_in[1];   // (1024,32)
    const float* W    = (const float*)d_in[2];   // (131072,128)
    const float* bias = (const float*)d_in[3];   // (128,)
    float* out = (float*)d_out;                  // (1024,128)

    cudaFuncSetAttribute(fipp_mma_kernel,
                         cudaFuncAttributeMaxDynamicSharedMemorySize, SMEM_TOTAL);

    fipp_prep_kernel<<<4096, 256>>>(W);
    fipp_mma_kernel<<<dim3(MTILES, SPLITS), 256, SMEM_TOTAL>>>(ctrl, pert);
    fipp_reduce_kernel<<<(BB * LL) / 4 / 256, 256>>>(bias, out);
}

// round 5
// speedup vs baseline: 4.8626x; 3.4888x over previous
#include <cuda_runtime.h>
#include <cstdint>

// ---------------- problem constants ----------------
#define BB 1024
#define LL 128
#define PP 32
#define SPLITS 16
#define LPER   8                  // l's per split
#define MTILES 8                  // 1024/128
#define NSTAGE 64                 // stages per CTA; stage = K=128 (one l, 4 i's)

// ---------------- device scratch (allocation-free) ----------------
__device__ float    g_partial[SPLITS * BB * LL];   // 8 MB split-K partials
__device__ uint32_t g_Wh[4096 * 2048];             // 32 MB: 64*W fp16 chunk images [chunk][n=128][k=32]

// ---------------- helpers ----------------
__device__ __forceinline__ uint32_t s2u(const void* p) {
    uint32_t a;
    asm("{ .reg .u64 t; cvta.to.shared.u64 t, %1; cvt.u32.u64 %0, t; }" : "=r"(a) : "l"(p));
    return a;
}
// pack two f32 -> f16x2 (lower half = lo, upper = hi)
__device__ __forceinline__ uint32_t pack_f16x2(float lo, float hi) {
    uint32_t r;
    asm("cvt.rn.f16x2.f32 %0, %1, %2;" : "=r"(r) : "f"(hi), "f"(lo));
    return r;
}
__device__ __forceinline__ void cp16(uint32_t sdst, const void* gsrc) {
    asm volatile("cp.async.cg.shared.global [%0], [%1], 16;" :: "r"(sdst), "l"(gsrc));
}
#define CP_COMMIT() asm volatile("cp.async.commit_group;")

#define LDSM4(r, a)                                                              \
    asm volatile("ldmatrix.sync.aligned.m8n8.x4.shared.b16 {%0,%1,%2,%3}, [%4];" \
                 : "=r"((r)[0]), "=r"((r)[1]), "=r"((r)[2]), "=r"((r)[3])        \
                 : "r"(a))

__device__ __forceinline__ void mma_acc(float* d, const uint32_t* a, uint32_t b0, uint32_t b1) {
    asm("mma.sync.aligned.m16n8k16.row.col.f32.f16.f16.f32 "
        "{%0,%1,%2,%3},{%4,%5,%6,%7},{%8,%9},{%0,%1,%2,%3};"
        : "+f"(d[0]), "+f"(d[1]), "+f"(d[2]), "+f"(d[3])
        : "r"(a[0]), "r"(a[1]), "r"(a[2]), "r"(a[3]), "r"(b0), "r"(b1));
}

// ---------------- SMEM layout (main kernel) ----------------
// B tile: [n=128][k=128 fp16] rows 256B padded -> 272B
#define ROWB    272
#define BMAT_SZ (128 * ROWB)              // 34816
#define OFF_PS  (2 * BMAT_SZ)             // 69632 : float pS[128][33]
#define OFF_CS  (OFF_PS + 128 * 33 * 4)   // 86528 : float cS[128][9]
#define SMEM_TOTAL (OFF_CS + 128 * 9 * 4) // 91136 bytes

// =====================================================================
// Prep: W fp32 [131072][128] -> per-chunk [n=128][k=32] fp16(64*W) images
// chunk = l*32+i (4096 chunks), image = 2048 u32 (8KB)
// =====================================================================
__global__ void __launch_bounds__(256) fipp_prep_kernel(const float* __restrict__ W)
{
    __shared__ float s[32][133];
    const int c = blockIdx.x, tid = threadIdx.x;
    const float4* src = (const float4*)(W + (size_t)c * 4096);
    for (int e = tid; e < 1024; e += 256) {
        float4 v = src[e];
        int j = e >> 5, n4 = (e & 31) << 2;
        s[j][n4] = v.x; s[j][n4 + 1] = v.y; s[j][n4 + 2] = v.z; s[j][n4 + 3] = v.w;
    }
    __syncthreads();
    uint32_t* oh = g_Wh + (size_t)c * 2048;
    for (int e = tid; e < 2048; e += 256) {
        const int n = e >> 4, jw = e & 15;
        oh[e] = pack_f16x2(64.0f * s[2 * jw][n], 64.0f * s[2 * jw + 1][n]);
    }
}

// =====================================================================
// Main: single fp16 HMMA GEMM. CTA: M=128 batch rows, N=128, K=8192.
// A fragments = fp16(c_l * p_i * p_j) rebuilt per i-chunk from resident
// fp32 p-constants; MMAs accumulate directly into register acc.
// =====================================================================
__global__ void __launch_bounds__(256, 1)
fipp_mma_kernel(const float* __restrict__ ctrl, const float* __restrict__ pert)
{
    extern __shared__ char smem[];
    float* pS = (float*)(smem + OFF_PS);   // [128][33]
    float* cS = (float*)(smem + OFF_CS);   // [128][9]
    const uint32_t sb = s2u(smem);
    const int tid = threadIdx.x, wid = tid >> 5, lane = tid & 31;
    const int wm = wid & 3, wn = wid >> 2;
    const int g = lane >> 2, t = lane & 3;
    const int bm0 = blockIdx.x * 128, l_base = blockIdx.y * LPER;

    // one-time p (padded 33) and c (padded 9) loads
    for (int e = tid; e < 128 * 32; e += 256) {
        int r = e >> 5, j = e & 31;
        pS[r * 33 + j] = pert[(size_t)(bm0 + r) * PP + j];
    }
    for (int e = tid; e < 128 * 8; e += 256) {
        int r = e >> 3, q = e & 7;
        cS[r * 9 + q] = ctrl[(size_t)(bm0 + r) * LL + l_base + q];
    }

    // B stage loader (double buffered): 4 chunk images -> [n][k=128] tile
    auto issueW = [&](int st, int buf) {
        const int l = st >> 3, i0 = (st & 7) * 4;
        const uint32_t* gh = g_Wh + (size_t)((l_base + l) * 32 + i0) * 2048;
        const uint32_t bbase = sb + (uint32_t)buf * BMAT_SZ;
        #pragma unroll
        for (int q = 0; q < 8; q++) {
            const int e = q * 256 + tid;        // 0..2047 16B groups
            const int c = e >> 9, gi = e & 511;
            const int n = gi >> 2, w4 = gi & 3;
            cp16(bbase + (uint32_t)(n * ROWB + (c << 6) + (w4 << 4)), gh + 4 * e);
        }
        CP_COMMIT();
    };

    issueW(0, 0);
    __syncthreads();   // pS/cS ready

    // per-thread rows and resident fp32 p-constants
    int rows[4];
    #pragma unroll
    for (int r = 0; r < 4; r++) rows[r] = wm * 32 + (r >> 1) * 16 + (r & 1) * 8 + g;
    float pc[4][8];
    #pragma unroll
    for (int r = 0; r < 4; r++)
        #pragma unroll
        for (int q = 0; q < 8; q++)
            pc[r][q] = pS[rows[r] * 33 + ((q >> 2) * 16 + ((q >> 1) & 1) * 8 + 2 * t + (q & 1))];

    float acc[2][8][4];
    #pragma unroll
    for (int m = 0; m < 2; m++)
        #pragma unroll
        for (int nt = 0; nt < 8; nt++)
            #pragma unroll
            for (int k = 0; k < 4; k++) acc[m][nt][k] = 0.f;

    float clv[4];

    // ldmatrix per-thread base: lane -> (matrix, row-in-8x8)
    const int nlocal = ((lane >> 4) << 3) | (lane & 7);
    const int koffm  = ((lane >> 3) & 1) << 4;
    const uint32_t tb = (uint32_t)((wn * 64 + nlocal) * ROWB + koffm);

    for (int st = 0; st < NSTAGE; st++) {
        const int buf = st & 1;
        if (st + 1 < NSTAGE) {
            issueW(st + 1, buf ^ 1);
            asm volatile("cp.async.wait_group 1;");
        } else {
            asm volatile("cp.async.wait_group 0;");
        }
        __syncthreads();

        const int l = st >> 3, i0 = (st & 7) * 4;
        if ((st & 7) == 0) {
            #pragma unroll
            for (int r = 0; r < 4; r++) clv[r] = cS[rows[r] * 9 + l];
        }
        const uint32_t Bh = sb + (uint32_t)buf * BMAT_SZ;

        #pragma unroll
        for (int c = 0; c < 4; c++) {
            // per-row scale s = ctrl[l] * pert[i0+c]
            float s4[4];
            #pragma unroll
            for (int r = 0; r < 4; r++) s4[r] = clv[r] * pS[rows[r] * 33 + i0 + c];

            // build pre-scaled fp16 A fragments: a = fp16(s * p_j)
            uint32_t a[2][2][4];
            #pragma unroll
            for (int m = 0; m < 2; m++)
                #pragma unroll
                for (int ks = 0; ks < 2; ks++)
                    #pragma unroll
                    for (int r4 = 0; r4 < 4; r4++) {
                        const int r = 2 * m + (r4 & 1);
                        const int q = ks * 4 + (r4 >> 1) * 2;
                        a[m][ks][r4] = pack_f16x2(s4[r] * pc[r][q], s4[r] * pc[r][q + 1]);
                    }

            #pragma unroll
            for (int ks = 0; ks < 2; ks++) {
                uint32_t bh[16];
                #pragma unroll
                for (int ntp = 0; ntp < 4; ntp++)
                    LDSM4(bh + 4 * ntp, Bh + tb + (uint32_t)(ntp * 16 * ROWB + c * 64 + ks * 32));
                #pragma unroll
                for (int m = 0; m < 2; m++)
                    #pragma unroll
                    for (int nt = 0; nt < 8; nt++)
                        mma_acc(acc[m][nt], a[m][ks], bh[2 * nt], bh[2 * nt + 1]);
            }
        }
        __syncthreads();   // protect buf before next issue overwrites
    }

    // epilogue -> split-K partials (undo the *64 on W)
    #pragma unroll
    for (int m = 0; m < 2; m++)
        #pragma unroll
        for (int rh = 0; rh < 2; rh++) {
            const int rowloc = wm * 32 + m * 16 + rh * 8 + g;
            float* dst = g_partial + ((size_t)blockIdx.y * BB + bm0 + rowloc) * LL;
            #pragma unroll
            for (int nt = 0; nt < 8; nt++) {
                const int col = wn * 64 + nt * 8 + 2 * t;
                float2 v;
                v.x = acc[m][nt][rh ? 2 : 0] * 0.015625f;
                v.y = acc[m][nt][rh ? 3 : 1] * 0.015625f;
                *(float2*)(dst + col) = v;
            }
        }
}

// =====================================================================
// Reduce: sum 16 split-K partials + bias
// =====================================================================
__global__ void __launch_bounds__(256)
fipp_reduce_kernel(const float* __restrict__ bias, float* __restrict__ out)
{
    const int i4 = blockIdx.x * blockDim.x + threadIdx.x;
    float4 acc = *(const float4*)(bias + ((i4 * 4) & (LL - 1)));
    #pragma unroll
    for (int s = 0; s < SPLITS; s++) {
        const float4 v = *(const float4*)(g_partial + (size_t)s * (BB * LL) + (size_t)i4 * 4);
        acc.x += v.x; acc.y += v.y; acc.z += v.z; acc.w += v.w;
    }
    *(float4*)(out + (size_t)i4 * 4) = acc;
}

extern "C" void kernel_launch(void* const* d_in, const int* in_sizes, int n_in,
                              void* d_out, int out_size)
{
    const float* ctrl = (const float*)d_in[0];   // (1024,128)
    const float* pert = (const float*)d_in[1];   // (1024,32)
    const float* W    = (const float*)d_in[2];   // (131072,128)
    const float* bias = (const float*)d_in[3];   // (128,)
    float* out = (float*)d_out;                  // (1024,128)

    cudaFuncSetAttribute(fipp_mma_kernel,
                         cudaFuncAttributeMaxDynamicSharedMemorySize, SMEM_TOTAL);

    fipp_prep_kernel<<<4096, 256>>>(W);
    fipp_mma_kernel<<<dim3(MTILES, SPLITS), 256, SMEM_TOTAL>>>(ctrl, pert);
    fipp_reduce_kernel<<<(BB * LL) / 4 / 256, 256>>>(bias, out);
}

// round 6
// speedup vs baseline: 5.2207x; 1.0737x over previous
#include <cuda_runtime.h>
#include <cstdint>

// ---------------- problem constants ----------------
#define BB 1024
#define LL 128
#define PP 32
#define SPLITS 16
#define LPER   8                  // l's per split
#define MTILES 8                  // 1024/128
#define NSTAGE 64                 // stages per CTA; stage = K=128 (one l, 4 i's)
#define NBUF   3

// ---------------- device scratch (allocation-free) ----------------
__device__ float    g_partial[SPLITS * BB * LL];   // 8 MB split-K partials
__device__ uint32_t g_Wh[4096 * 2048];             // 32 MB: 64*W fp16 chunk images [chunk][n=128][k=32]

// ---------------- helpers ----------------
__device__ __forceinline__ uint32_t s2u(const void* p) {
    uint32_t a;
    asm("{ .reg .u64 t; cvta.to.shared.u64 t, %1; cvt.u32.u64 %0, t; }" : "=r"(a) : "l"(p));
    return a;
}
// pack two f32 -> f16x2 (lower half = lo, upper = hi)
__device__ __forceinline__ uint32_t pack_f16x2(float lo, float hi) {
    uint32_t r;
    asm("cvt.rn.f16x2.f32 %0, %1, %2;" : "=r"(r) : "f"(hi), "f"(lo));
    return r;
}
__device__ __forceinline__ void cp16(uint32_t sdst, const void* gsrc) {
    asm volatile("cp.async.cg.shared.global [%0], [%1], 16;" :: "r"(sdst), "l"(gsrc));
}
#define CP_COMMIT() asm volatile("cp.async.commit_group;")
#define CP_WAIT(n)  asm volatile("cp.async.wait_group %0;" :: "n"(n))

#define LDSM4(r, a)                                                              \
    asm volatile("ldmatrix.sync.aligned.m8n8.x4.shared.b16 {%0,%1,%2,%3}, [%4];" \
                 : "=r"((r)[0]), "=r"((r)[1]), "=r"((r)[2]), "=r"((r)[3])        \
                 : "r"(a))

__device__ __forceinline__ void mma_acc(float* d, const uint32_t* a, uint32_t b0, uint32_t b1) {
    asm("mma.sync.aligned.m16n8k16.row.col.f32.f16.f16.f32 "
        "{%0,%1,%2,%3},{%4,%5,%6,%7},{%8,%9},{%0,%1,%2,%3};"
        : "+f"(d[0]), "+f"(d[1]), "+f"(d[2]), "+f"(d[3])
        : "r"(a[0]), "r"(a[1]), "r"(a[2]), "r"(a[3]), "r"(b0), "r"(b1));
}

// ---------------- SMEM layout (main kernel) ----------------
// B tile: [n=128][k=128 fp16], 256B rows, 16B-unit XOR swizzle u^(n&7)
#define ROWB    256
#define BMAT_SZ (128 * ROWB)                  // 32768
#define OFF_PS  (NBUF * BMAT_SZ)              // 98304 : float pS[128][33]
#define OFF_CS  (OFF_PS + 128 * 33 * 4)       // float cS[128][9]
#define SMEM_TOTAL (OFF_CS + 128 * 9 * 4)     // 120320 bytes

// =====================================================================
// Prep: W fp32 [131072][128] -> per-chunk [n=128][k=32] fp16(64*W) images
// =====================================================================
__global__ void __launch_bounds__(256) fipp_prep_kernel(const float* __restrict__ W)
{
    __shared__ float s[32][133];
    const int c = blockIdx.x, tid = threadIdx.x;
    const float4* src = (const float4*)(W + (size_t)c * 4096);
    for (int e = tid; e < 1024; e += 256) {
        float4 v = src[e];
        int j = e >> 5, n4 = (e & 31) << 2;
        s[j][n4] = v.x; s[j][n4 + 1] = v.y; s[j][n4 + 2] = v.z; s[j][n4 + 3] = v.w;
    }
    __syncthreads();
    uint32_t* oh = g_Wh + (size_t)c * 2048;
    for (int e = tid; e < 2048; e += 256) {
        const int n = e >> 4, jw = e & 15;
        oh[e] = pack_f16x2(64.0f * s[2 * jw][n], 64.0f * s[2 * jw + 1][n]);
    }
}

// =====================================================================
// Main: single fp16 HMMA GEMM. CTA: M=128 batch rows, N=128, K=8192.
// =====================================================================
__global__ void __launch_bounds__(256, 1)
fipp_mma_kernel(const float* __restrict__ ctrl, const float* __restrict__ pert)
{
    extern __shared__ char smem[];
    float* pS = (float*)(smem + OFF_PS);   // [128][33]
    float* cS = (float*)(smem + OFF_CS);   // [128][9]
    const uint32_t sb = s2u(smem);
    const int tid = threadIdx.x, wid = tid >> 5, lane = tid & 31;
    const int wm = wid & 3, wn = wid >> 2;
    const int g = lane >> 2, t = lane & 3;
    const int bm0 = blockIdx.x * 128, l_base = blockIdx.y * LPER;

    // one-time p (padded 33) and c (padded 9) loads
    for (int e = tid; e < 128 * 32; e += 256) {
        int r = e >> 5, j = e & 31;
        pS[r * 33 + j] = pert[(size_t)(bm0 + r) * PP + j];
    }
    for (int e = tid; e < 128 * 8; e += 256) {
        int r = e >> 3, q = e & 7;
        cS[r * 9 + q] = ctrl[(size_t)(bm0 + r) * LL + l_base + q];
    }

    // B stage loader: 4 chunk images -> [n][k=128] tile, swizzled 16B units
    auto issueW = [&](int st, int buf) {
        const int l = st >> 3, i0 = (st & 7) * 4;
        const uint32_t* gh = g_Wh + (size_t)((l_base + l) * 32 + i0) * 2048;
        const uint32_t bbase = sb + (uint32_t)buf * BMAT_SZ;
        #pragma unroll
        for (int q = 0; q < 8; q++) {
            const int e = q * 256 + tid;        // 0..2047 16B units
            const int c = e >> 9, gi = e & 511;
            const int n = gi >> 2, w4 = gi & 3;
            const int u = ((4 * c + w4) ^ (n & 7));
            cp16(bbase + (uint32_t)(n * ROWB + (u << 4)), gh + 4 * e);
        }
        CP_COMMIT();
    };

    issueW(0, 0);
    issueW(1, 1);
    __syncthreads();   // pS/cS ready

    // per-thread rows and resident fp32 p-constants
    int rows[4];
    #pragma unroll
    for (int r = 0; r < 4; r++) rows[r] = wm * 32 + (r >> 1) * 16 + (r & 1) * 8 + g;
    float pc[4][8];
    #pragma unroll
    for (int r = 0; r < 4; r++)
        #pragma unroll
        for (int q = 0; q < 8; q++)
            pc[r][q] = pS[rows[r] * 33 + ((q >> 2) * 16 + ((q >> 1) & 1) * 8 + 2 * t + (q & 1))];

    float acc[2][8][4];
    #pragma unroll
    for (int m = 0; m < 2; m++)
        #pragma unroll
        for (int nt = 0; nt < 8; nt++)
            #pragma unroll
            for (int k = 0; k < 4; k++) acc[m][nt][k] = 0.f;

    float clv[4];

    // ldmatrix addressing: row base per lane + per-lane swizzle constants
    const int nlocal = ((lane >> 4) << 3) | (lane & 7);
    const int hk = (lane >> 3) & 1;          // 16B k-offset select
    const int sx = lane & 7;                 // swizzle XOR
    const uint32_t rba = (uint32_t)((wn * 64 + nlocal) * ROWB);

    for (int st = 0; st < NSTAGE; st++) {
        const int buf = st % NBUF;
        if (st + 2 < NSTAGE) { CP_WAIT(1); } else { CP_WAIT(0); }
        __syncthreads();
        if (st + 2 < NSTAGE) issueW(st + 2, (st + 2) % NBUF);

        const int l = st >> 3, i0 = (st & 7) * 4;
        if ((st & 7) == 0) {
            #pragma unroll
            for (int r = 0; r < 4; r++) clv[r] = cS[rows[r] * 9 + l];
        }
        const uint32_t Bt = sb + (uint32_t)buf * BMAT_SZ + rba;

        // fragment-group loader: group idx gidx = c*2+ks
        auto ld_group = [&](int gidx, uint32_t* bh) {
            const uint32_t uu = (uint32_t)(((gidx << 1) + hk) ^ sx) << 4;
            #pragma unroll
            for (int ntp = 0; ntp < 4; ntp++)
                LDSM4(bh + 4 * ntp, Bt + (uint32_t)(ntp * 16 * ROWB) + uu);
        };

        uint32_t bhA[16], bhB[16];
        ld_group(0, bhA);

        float s4[4];
        #pragma unroll
        for (int gidx = 0; gidx < 8; gidx++) {
            const int c = gidx >> 1, ks = gidx & 1;
            uint32_t* cur = (gidx & 1) ? bhB : bhA;
            uint32_t* nxt = (gidx & 1) ? bhA : bhB;
            if (gidx + 1 < 8) ld_group(gidx + 1, nxt);

            if (ks == 0) {
                #pragma unroll
                for (int r = 0; r < 4; r++) s4[r] = clv[r] * pS[rows[r] * 33 + i0 + c];
            }

            // build pre-scaled fp16 A fragments for this (c,ks)
            uint32_t a[2][4];
            #pragma unroll
            for (int m = 0; m < 2; m++)
                #pragma unroll
                for (int r4 = 0; r4 < 4; r4++) {
                    const int r = 2 * m + (r4 & 1);
                    const int q = ks * 4 + (r4 >> 1) * 2;
                    a[m][r4] = pack_f16x2(s4[r] * pc[r][q], s4[r] * pc[r][q + 1]);
                }

            #pragma unroll
            for (int m = 0; m < 2; m++)
                #pragma unroll
                for (int nt = 0; nt < 8; nt++)
                    mma_acc(acc[m][nt], a[m], cur[2 * nt], cur[2 * nt + 1]);
        }
    }

    // epilogue -> split-K partials (undo the *64 on W)
    #pragma unroll
    for (int m = 0; m < 2; m++)
        #pragma unroll
        for (int rh = 0; rh < 2; rh++) {
            const int rowloc = wm * 32 + m * 16 + rh * 8 + g;
            float* dst = g_partial + ((size_t)blockIdx.y * BB + bm0 + rowloc) * LL;
            #pragma unroll
            for (int nt = 0; nt < 8; nt++) {
                const int col = wn * 64 + nt * 8 + 2 * t;
                float2 v;
                v.x = acc[m][nt][rh ? 2 : 0] * 0.015625f;
                v.y = acc[m][nt][rh ? 3 : 1] * 0.015625f;
                *(float2*)(dst + col) = v;
            }
        }
}

// =====================================================================
// Reduce: sum 16 split-K partials + bias
// =====================================================================
__global__ void __launch_bounds__(256)
fipp_reduce_kernel(const float* __restrict__ bias, float* __restrict__ out)
{
    const int i4 = blockIdx.x * blockDim.x + threadIdx.x;
    float4 acc = *(const float4*)(bias + ((i4 * 4) & (LL - 1)));
    #pragma unroll
    for (int s = 0; s < SPLITS; s++) {
        const float4 v = *(const float4*)(g_partial + (size_t)s * (BB * LL) + (size_t)i4 * 4);
        acc.x += v.x; acc.y += v.y; acc.z += v.z; acc.w += v.w;
    }
    *(float4*)(out + (size_t)i4 * 4) = acc;
}

extern "C" void kernel_launch(void* const* d_in, const int* in_sizes, int n_in,
                              void* d_out, int out_size)
{
    const float* ctrl = (const float*)d_in[0];   // (1024,128)
    const float* pert = (const float*)d_in[1];   // (1024,32)
    const float* W    = (const float*)d_in[2];   // (131072,128)
    const float* bias = (const float*)d_in[3];   // (128,)
    float* out = (float*)d_out;                  // (1024,128)

    cudaFuncSetAttribute(fipp_mma_kernel,
                         cudaFuncAttributeMaxDynamicSharedMemorySize, SMEM_TOTAL);

    fipp_prep_kernel<<<4096, 256>>>(W);
    fipp_mma_kernel<<<dim3(MTILES, SPLITS), 256, SMEM_TOTAL>>>(ctrl, pert);
    fipp_reduce_kernel<<<(BB * LL) / 4 / 256, 256>>>(bias, out);
}